// round 17
// baseline (speedup 1.0000x reference)
#include <cuda_runtime.h>
#include <math.h>

// Problem constants (fixed by the reference)
#define N_K        16
#define C_CAT      136          // 16*17/2 upper-tri pairs
#define C_PAD      160          // padded to 32*5 for a uniform unrolled loop
#define DIM        64
#define MU_PITCH   68           // DIM + 4 pad: rows 16B-aligned
#define NROWS      8192         // 512 * 16
#define ROWS_PER_BLK 16         // 16 warps x 1 row
#define NTHR       512
#define MAIN_BLOCKS (NROWS / ROWS_PER_BLK)   // 512

#define LOG2PI_F   1.8378770664093453f
#define LN2_F      0.6931471805599453f
#define L2E_F      1.4426950408889634f
// Phi-tanh approx: Phi(x) ~= 0.5*(1+tanh(C1*x + C3*x^3))
#define PHI_C1     0.7978845608028654f
#define PHI_C3     0.03567740813712f

// ---- device scratch (static globals; no allocation) ----
__device__ float  d_partials[MAIN_BLOCKS];
__device__ unsigned int d_counter = 0;

__device__ __forceinline__ float tanh_approx(float x) {
    float r; asm("tanh.approx.f32 %0, %1;" : "=f"(r) : "f"(x)); return r;
}
__device__ __forceinline__ float ex2_approx(float x) {
    float r; asm("ex2.approx.f32 %0, %1;" : "=f"(r) : "f"(x)); return r;
}

// ---------------------------------------------------------------------------
// SINGLE fused kernel. 16 rows/block (512 thr, 16 warps), ONE row per warp.
// 8192 warps total -> ~55 warps/SM: maximum latency cover for this
// dependency-bound kernel.  Lean log2-domain scalar hot loop; g via
// conflict-free LDS; cheap per-block prologue; last-block finalize.
// Diagonal pairs encoded as heavy categories (k1L=0, recipX=0 -> nu=0;
// s=20 -> D=1). Slots [136,160): baseC2=-1e30 (ex2 -> 0).
// ---------------------------------------------------------------------------
__global__ __launch_bounds__(NTHR, 4) void fused_kernel(const float* __restrict__ z,
                                                        const float* __restrict__ pi,
                                                        const float* __restrict__ mu,
                                                        float* __restrict__ out)
{
    __shared__ float  mu_t[N_K][MU_PITCH];          // transposed mu
    __shared__ float  z_s [ROWS_PER_BLK][DIM];      // 4 KB
    __shared__ float  g_sL[ROWS_PER_BLK][N_K];      // g * log2e per row
    __shared__ float  g_gram[N_K][N_K + 1];         // Gram(mu_k, mu_j)
    __shared__ float4 c4_s[C_PAD];                  // {k1L, recipX, s, baseC2}
    __shared__ int    ab_s[C_PAD];                  // A | B<<8
    __shared__ float  rowres[ROWS_PER_BLK];
    __shared__ float  red[NTHR];
    __shared__ int    s_is_last;

    const int t = threadIdx.x;
    const int w = t >> 5;        // warp 0..15; handles row w
    const int l = t & 31;

    // ---- z prefetch: this warp's row, 2 scalars per lane ----
    const int row0 = blockIdx.x * ROWS_PER_BLK;
    const float* zp = z + (row0 + w) * DIM;
    const float zl0 = zp[l];
    const float zl1 = zp[l + 32];

    // stage mu transposed (2 iterations at 512 threads)
    for (int i = t; i < DIM * N_K; i += NTHR) {
        const int d = i >> 4, k = i & 15;           // mu is [d][k]
        mu_t[k][d] = mu[i];
    }
    // stage z
    z_s[w][l]      = zl0;
    z_s[w][l + 32] = zl1;
    // padding category slots
    if (t >= C_CAT && t < C_PAD) {
        c4_s[t] = make_float4(0.f, 0.f, 20.f, -1e30f);
        ab_s[t] = 0;
    }

    // warp-local softmax denominator -- only warps 0..4 (feed threads < 136)
    float lgden = 0.f;
    if (w < 5) {
        const float v0 = pi[l], v1 = pi[l + 32], v2 = pi[l + 64], v3 = pi[l + 96];
        const float v4 = (l < 8) ? pi[128 + l] : -INFINITY;
        float mx = fmaxf(fmaxf(fmaxf(v0, v1), fmaxf(v2, v3)), v4);
        #pragma unroll
        for (int o = 16; o; o >>= 1) mx = fmaxf(mx, __shfl_xor_sync(0xffffffffu, mx, o));
        float sm = __expf(v0 - mx) + __expf(v1 - mx) + __expf(v2 - mx) + __expf(v3 - mx)
                 + ((l < 8) ? __expf(v4 - mx) : 0.f);
        #pragma unroll
        for (int o = 16; o; o >>= 1) sm += __shfl_xor_sync(0xffffffffu, sm, o);
        lgden = mx + __logf(sm);
    }

    // 0.5*|z|^2 for this row
    float p = zl0 * zl0 + zl1 * zl1;
    #pragma unroll
    for (int o = 16; o; o >>= 1) p += __shfl_xor_sync(0xffffffffu, p, o);

    __syncthreads();                                 // mu_t & z_s ready

    // ---- Gram pass: thread c (<136) computes dot(mu_A, mu_B), one pass ----
    int Ad = 0, Bd = 0;
    if (t < C_CAT) {
        const float cf = (float)t;
        Ad = (int)floorf((33.0f - sqrtf(fmaf(-8.0f, cf, 1089.0f))) * 0.5f);
        Bd = t - ((33 - Ad) * Ad >> 1) + Ad;         // f(A) = A*(33-A)/2

        const float4* ma = (const float4*)&mu_t[Ad][0];
        const float4* mb = (const float4*)&mu_t[Bd][0];
        float a0 = 0.f, a1 = 0.f, a2 = 0.f, a3 = 0.f;
        #pragma unroll
        for (int j = 0; j < 16; ++j) {
            const float4 fa = ma[j];
            const float4 fb = mb[j];
            a0 = fmaf(fa.x, fb.x, a0); a1 = fmaf(fa.y, fb.y, a1);
            a2 = fmaf(fa.z, fb.z, a2); a3 = fmaf(fa.w, fb.w, a3);
        }
        const float g = (a0 + a1) + (a2 + a3);
        g_gram[Ad][Bd] = g;
        g_gram[Bd][Ad] = g;
    }
    __syncthreads();                                 // Gram ready

    // ---- per-category constants from Gram (log2 domain) ----
    if (t < C_CAT) {
        const float GAA = g_gram[Ad][Ad];
        const float GAB = g_gram[Ad][Bd];
        const float GBB = g_gram[Bd][Bd];
        const float invsig = (GAA - 2.0f * GAB) + GBB;
        const float lp = -32.0f * LOG2PI_F + (__ldg(&pi[t]) - lgden);

        float baseC, recipX, s, k1L;
        if (Ad == Bd) {                      // diag: inv_sig == 0 exactly
            baseC = lp - 0.5f * GBB; recipX = 0.f; s = 20.f; k1L = 0.f;
        } else {
            const float clip_is = fminf(fmaxf(invsig, 1e-12f), 1e30f);
            s      = sqrtf(clip_is);
            baseC  = lp + 0.5f * (LOG2PI_F - __logf(clip_is)) - LN2_F - 0.5f * GBB;
            recipX = (1.0f / invsig) * (1.0f / L2E_F);
            k1L    = (GBB - GAB) * L2E_F;    // dot(alpha, mu_B) * log2e
        }
        c4_s[t] = make_float4(k1L, recipX, s, baseC * L2E_F);
        ab_s[t] = Ad | (Bd << 8);
    }
    __syncthreads();                                 // constants ready

    // g-dot for this row: lane (k=l&15, h=l>>4) does dims [32h, 32h+32)
    {
        const int k = l & 15, h = l >> 4;
        const float4* mr = (const float4*)&mu_t[k][h * 32];
        const float4* zr = (const float4*)&z_s[w][h * 32];
        float a0 = 0.f, a1 = 0.f, a2 = 0.f, a3 = 0.f;
        #pragma unroll
        for (int j = 0; j < 8; ++j) {
            const float4 mv = mr[j];
            const float4 q0 = zr[j];
            a0 = fmaf(q0.x, mv.x, a0); a1 = fmaf(q0.y, mv.y, a1);
            a2 = fmaf(q0.z, mv.z, a2); a3 = fmaf(q0.w, mv.w, a3);
        }
        float acc = (a0 + a1) + (a2 + a3);
        acc += __shfl_xor_sync(0xffffffffu, acc, 16);
        if (l < N_K) g_sL[w][l] = acc * L2E_F;       // g * log2e
    }
    __syncwarp();

    // ---- bC2max = max_c baseC2 ----
    float bmax = c4_s[l].w;
    #pragma unroll
    for (int i = 1; i < 5; ++i) bmax = fmaxf(bmax, c4_s[l + 32 * i].w);
    #pragma unroll
    for (int o = 16; o; o >>= 1) bmax = fmaxf(bmax, __shfl_xor_sync(0xffffffffu, bmax, o));
    const float bC2max = bmax;

    // per-row shift (z2h cancels exactly in rowres)
    const float nSh = -fmaf(0.5f * p, L2E_F, bC2max);
    const float* gr = &g_sL[w][0];

    // ---- hot loop: 5 categories per lane, scalar, fully unrolled ----
    float ss = 0.f;
    #pragma unroll
    for (int i = 0; i < 5; ++i) {
        const int c = l + 32 * i;
        const float4 q4 = c4_s[c];                  // k1L, recipX, s, baseC2
        const int ab = ab_s[c];
        const float gA = gr[ab & 15];
        const float gB = gr[(ab >> 8) & 15];

        const float deL = (q4.x - gB) + gA;         // delta * log2e
        const float nu  = deL * q4.y;               // true nu
        const float xs  = fmaf(0.5f * deL, nu, (q4.w + gB) + nSh);  // log2 exponent

        const float ns  = nu * q4.z;
        const float e1  = q4.z - ns;                // eta1 = (1-nu)*s
        const float e2  = -ns;                      // eta2 = -nu*s
        const float u1  = e1 * fmaf(PHI_C3, e1 * e1, PHI_C1);
        const float u2  = e2 * fmaf(PHI_C3, e2 * e2, PHI_C1);
        const float D   = fmaxf(tanh_approx(u1) - tanh_approx(u2), 2e-16f);
        ss = fmaf(ex2_approx(xs), D, ss);
    }

    // warp sum of ss
    #pragma unroll
    for (int o = 16; o; o >>= 1) ss += __shfl_xor_sync(0xffffffffu, ss, o);

    // rowres = bC2max*ln2 + log(ss)
    if (l == 0)
        rowres[w] = fmaf(bC2max, LN2_F, __logf(fmaxf(ss, 1e-37f)));
    __syncthreads();

    // ---- per-block partial + last-block-done finalize ----
    if (t == 0) {
        float s = 0.f;
        #pragma unroll
        for (int r = 0; r < ROWS_PER_BLK; ++r) s += rowres[r];
        d_partials[blockIdx.x] = s;
        __threadfence();
        const unsigned int ticket = atomicAdd(&d_counter, 1u);
        s_is_last = (ticket == (unsigned)(gridDim.x - 1));
    }
    __syncthreads();

    if (s_is_last) {
        float s = 0.f;
        if (t < MAIN_BLOCKS / 4) {
            const float4 v = __ldcg(((const float4*)d_partials) + t);
            s = (v.x + v.y) + (v.z + v.w);
        }
        red[t] = s; __syncthreads();
        for (int o = NTHR / 2; o; o >>= 1) { if (t < o) red[t] += red[t + o]; __syncthreads(); }
        if (t == 0) {
            out[0] = red[0] * (1.0f / (float)NROWS);
            d_counter = 0;                 // reset for next graph replay
        }
    }
}

// ---------------------------------------------------------------------------
extern "C" void kernel_launch(void* const* d_in, const int* in_sizes, int n_in,
                              void* d_out, int out_size)
{
    (void)in_sizes; (void)n_in; (void)out_size;
    const float* z  = (const float*)d_in[0];
    const float* pi = (const float*)d_in[1];
    const float* mu = (const float*)d_in[2];
    float* out = (float*)d_out;

    fused_kernel<<<MAIN_BLOCKS, NTHR>>>(z, pi, mu, out);
}